// round 15
// baseline (speedup 1.0000x reference)
#include <cuda_runtime.h>

// PyramidROIAlign: B=2, N=1000 boxes, C=256, 7x7 pool. Single fused kernel.
// R12 champion structure (128-thread CTA = 8 items, guarded param phase ->
// barrier -> 16-lanes/item unroll-4 gather, regs pinned, __stcs stores) with
// the lerp rewritten in bilinear-weight form using packed f32x2 FMA
// (4 packed instrs per float4 instead of 24 scalar FADD/FFMA).

#define POOL 7
#define NPTS (POOL * POOL)
#define CCH 256
#define LANES 16
#define ITEMS_PER_CTA 8
#define CTA_THREADS 128

typedef unsigned long long u64;

__device__ __forceinline__ u64 f32x2_pack(float lo, float hi) {
    u64 r; asm("mov.b64 %0, {%1, %2};" : "=l"(r) : "f"(lo), "f"(hi)); return r;
}
__device__ __forceinline__ u64 f32x2_mul(u64 a, u64 b) {
    u64 r; asm("mul.rn.f32x2 %0, %1, %2;" : "=l"(r) : "l"(a), "l"(b)); return r;
}
__device__ __forceinline__ u64 f32x2_fma(u64 a, u64 b, u64 c) {
    u64 r; asm("fma.rn.f32x2 %0, %1, %2, %3;" : "=l"(r) : "l"(a), "l"(b), "l"(c)); return r;
}

__global__ void __launch_bounds__(CTA_THREADS, 16)
roi_fused_kernel(const float* __restrict__ boxes,
                 const float* __restrict__ image_shape,
                 const float* __restrict__ P2,
                 const float* __restrict__ P3,
                 const float* __restrict__ P4,
                 const float* __restrict__ P5,
                 float* __restrict__ out,
                 int total_items, int boxes_per_batch)
{
    __shared__ ulonglong4 s_addr[ITEMS_PER_CTA];
    __shared__ float4     s_w[ITEMS_PER_CTA];   // 4 bilinear weights

    const int item_base = blockIdx.x * ITEMS_PER_CTA;
    const int tid = threadIdx.x;

    if (tid < ITEMS_PER_CTA) {
        const int item = item_base + tid;
        if (item < total_items) {
            const int bn = item / NPTS;
            const int pt = item - bn * NPTS;
            const int py = pt / POOL;
            const int px = pt - py * POOL;
            const int b  = bn / boxes_per_batch;

            const float4 bx = ((const float4*)boxes)[bn];
            const float y1 = bx.x, x1 = bx.y, y2 = bx.z, x2 = bx.w;
            const float h = y2 - y1;
            const float w = x2 - x1;

            // Level selection — exact reference fp32 op order; rintf == jnp.round.
            const float area = image_shape[0] * image_shape[1];
            float lvlf = log2f(sqrtf(h * w) / (224.0f / sqrtf(area)));
            lvlf = fminf(5.0f, fmaxf(2.0f, 4.0f + rintf(lvlf)));
            const int lvl = (int)lvlf;

            const float* fmap;
            int H;
            if (lvl == 2)      { fmap = P2; H = 256; }
            else if (lvl == 3) { fmap = P3; H = 128; }
            else if (lvl == 4) { fmap = P4; H = 64;  }
            else               { fmap = P5; H = 32;  }
            const int W = H;

            // Reference order: in_y = (y1 + h*gy) * (H-1)
            const float gy = (float)py * (1.0f / 6.0f);
            const float gx = (float)px * (1.0f / 6.0f);
            const float in_y = (y1 + h * gy) * (float)(H - 1);
            const float in_x = (x1 + w * gx) * (float)(W - 1);

            const float y0f = floorf(in_y);
            const float x0f = floorf(in_x);
            const float wy = in_y - y0f;
            const float wx = in_x - x0f;

            int y0  = min(max((int)y0f, 0), H - 1);
            int y1i = min(y0 + 1, H - 1);
            int x0  = min(max((int)x0f, 0), W - 1);
            int x1i = min(x0 + 1, W - 1);

            const unsigned long long base =
                (unsigned long long)fmap + (unsigned long long)b * H * W * CCH * 4ull;
            const unsigned long long rowT = base + (unsigned long long)(y0  * W) * (CCH * 4ull);
            const unsigned long long rowB = base + (unsigned long long)(y1i * W) * (CCH * 4ull);

            ulonglong4 a;
            a.x = rowT + (unsigned long long)x0  * (CCH * 4ull);
            a.y = rowT + (unsigned long long)x1i * (CCH * 4ull);
            a.z = rowB + (unsigned long long)x0  * (CCH * 4ull);
            a.w = rowB + (unsigned long long)x1i * (CCH * 4ull);
            s_addr[tid] = a;

            // Bilinear weights (weight-form lerp; ~ulp-level diff vs reference)
            const float iwx = 1.0f - wx;
            const float iwy = 1.0f - wy;
            s_w[tid] = make_float4(iwx * iwy,   // tl
                                   wx  * iwy,   // tr
                                   iwx * wy,    // bl
                                   wx  * wy);   // br
        }
    }
    __syncthreads();

    const int local = tid >> 4;            // item within CTA (0..7)
    const int lane  = tid & (LANES - 1);   // float4 lane group
    const int item = item_base + local;
    if (item >= total_items) return;

    const ulonglong4 a = s_addr[local];    // SMEM broadcast
    const float4 wv = s_w[local];
    const u64 w0 = f32x2_pack(wv.x, wv.x);
    const u64 w1 = f32x2_pack(wv.y, wv.y);
    const u64 w2 = f32x2_pack(wv.z, wv.z);
    const u64 w3 = f32x2_pack(wv.w, wv.w);

    const ulonglong2* __restrict__ tl = (const ulonglong2*)a.x;
    const ulonglong2* __restrict__ tr = (const ulonglong2*)a.y;
    const ulonglong2* __restrict__ bl = (const ulonglong2*)a.z;
    const ulonglong2* __restrict__ br = (const ulonglong2*)a.w;
    double2* __restrict__ o = (double2*)(out + (size_t)item * CCH);

#pragma unroll
    for (int j = 0; j < 4; j++) {
        const int c = lane + j * LANES;
        const ulonglong2 vtl = tl[c];
        const ulonglong2 vtr = tr[c];
        const ulonglong2 vbl = bl[c];
        const ulonglong2 vbr = br[c];

        // r = br*w3 + bl*w2 + tr*w1 + tl*w0   (packed f32x2, 4 instrs per half)
        u64 r0 = f32x2_mul(vbr.x, w3);
        r0 = f32x2_fma(vbl.x, w2, r0);
        r0 = f32x2_fma(vtr.x, w1, r0);
        r0 = f32x2_fma(vtl.x, w0, r0);
        u64 r1 = f32x2_mul(vbr.y, w3);
        r1 = f32x2_fma(vbl.y, w2, r1);
        r1 = f32x2_fma(vtr.y, w1, r1);
        r1 = f32x2_fma(vtl.y, w0, r1);

        double2 rd;
        rd.x = __longlong_as_double((long long)r0);
        rd.y = __longlong_as_double((long long)r1);
        __stcs(&o[c], rd);
    }
}

extern "C" void kernel_launch(void* const* d_in, const int* in_sizes, int n_in,
                              void* d_out, int out_size)
{
    const float* boxes = (const float*)d_in[0];
    const float* ishp  = (const float*)d_in[1];
    const float* P2    = (const float*)d_in[2];
    const float* P3    = (const float*)d_in[3];
    const float* P4    = (const float*)d_in[4];
    const float* P5    = (const float*)d_in[5];
    float* out = (float*)d_out;

    const int B = in_sizes[2] / (256 * 256 * 256);
    const int total_boxes = in_sizes[0] / 4;
    const int boxes_per_batch = total_boxes / B;
    const int total_items = total_boxes * NPTS;

    const int blocks = (total_items + ITEMS_PER_CTA - 1) / ITEMS_PER_CTA;
    roi_fused_kernel<<<blocks, CTA_THREADS>>>(boxes, ishp, P2, P3, P4, P5, out,
                                              total_items, boxes_per_batch);
}